// round 7
// baseline (speedup 1.0000x reference)
#include <cuda_runtime.h>
#include <cstdint>

// Problem constants
#define NPTS 200000
#define NCLS 20
#define NPROP 256
#define NPAIR 400000
#define THRESH 100

// Derived
#define WPP (NPTS / 32)                 // 6250 words per proposal
#define WORDS ((size_t)NPROP * WPP)     // 1,600,000 words

// Output layout (float32, concatenated in return order)
#define OFF_SCORES  ((size_t)0)
#define OFF_MASKS   ((size_t)256)
#define OFF_CLASSES ((size_t)(256 + (size_t)NPROP * NPTS))
#define OFF_BIAS    (OFF_CLASSES + 256)
#define OFF_PROBS   (OFF_BIAS + (size_t)NPTS * 3)

#define PAD 32   // 128B stride between per-proposal counters (distinct L2 lines)

// Scratch (device globals: allocation-free)
__device__ unsigned int g_bits[WORDS];          // 6.4 MB dedupe bitmask
__device__ int   g_rep_p[NPROP * PAD];
__device__ int   g_count_p[NPROP * PAD];
__device__ float g_score_p[NPROP * PAD];
__device__ int   g_segpred[NPTS];

// Fast exp on FMA pipe (no MUFU). rel err ~2e-6.
__device__ __forceinline__ float fexp(float x) {
    const float MAGIC = 12582912.0f;           // 1.5 * 2^23
    float t = fmaf(x, 1.4426950408889634f, MAGIC);
    int   n = __float_as_int(t) - 0x4B400000;
    float f = fmaf(x, 1.4426950408889634f, -(t - MAGIC));
    float p = 1.3333558146e-3f;
    p = fmaf(p, f, 9.6181291076e-3f);
    p = fmaf(p, f, 5.5504108664e-2f);
    p = fmaf(p, f, 2.4022650696e-1f);
    p = fmaf(p, f, 6.9314718056e-1f);
    p = fmaf(p, f, 1.0f);
    return __int_as_float(__float_as_int(p) + (n << 23));
}

// --- stream 0: zero bitmask ---
__global__ void k_zero_bits() {
    size_t t = (size_t)blockIdx.x * blockDim.x + threadIdx.x;
    if (t < WORDS / 4) ((uint4*)g_bits)[t] = make_uint4(0u, 0u, 0u, 0u);
}

// --- stream 0 (right after zero): pure dedupe scatter, no other deps ---
__global__ void __launch_bounds__(1024)
k_scatter_lite(const int* __restrict__ pid, const int* __restrict__ nid) {
    int m = blockIdx.x * blockDim.x + threadIdx.x;
    if (m >= NPAIR) return;
    size_t bit = (size_t)pid[m] * NPTS + nid[m];
    atomicOr(&g_bits[bit >> 5], 1u << (bit & 31u));
}

// --- stream C: init padded counters ---
__global__ void k_init_small() {
    int t = blockIdx.x * blockDim.x + threadIdx.x;
    if (t < NPROP * PAD) {
        g_rep_p[t]   = 0x7FFFFFFF;
        g_count_p[t] = 0;
        g_score_p[t] = 0.0f;
    }
}

// --- stream D: bias passthrough (independent) ---
__global__ void k_bias(const float* __restrict__ bias, float* __restrict__ bias_out) {
    int t = blockIdx.x * blockDim.x + threadIdx.x;
    if (t < NPTS * 3 / 4) ((float4*)bias_out)[t] = ((const float4*)bias)[t];
}

// --- stream B: staged softmax + argmax (padded smem rows, FMA exp) ---
__global__ void k_softmax(const float* __restrict__ logit,
                          float* __restrict__ probs_out) {
    __shared__ float s[256 * 21];   // 21 KB
    int tid  = threadIdx.x;
    int base = blockIdx.x * 256;
    int count = NPTS - base;
    if (count > 256) count = 256;
    int tot = count * NCLS;

    const float* src = logit + (size_t)base * NCLS;
    for (int i = tid; i < tot; i += 256) {
        int row = i / NCLS, col = i - row * NCLS;
        s[row * 21 + col] = src[i];
    }
    __syncthreads();

    if (tid < count) {
        float* row = s + tid * 21;
        float v[NCLS];
#pragma unroll
        for (int i = 0; i < NCLS; i++) v[i] = row[i];
        float m = v[0]; int am = 0;
#pragma unroll
        for (int i = 1; i < NCLS; i++) if (v[i] > m) { m = v[i]; am = i; }
        float e[NCLS]; float sum = 0.0f;
#pragma unroll
        for (int i = 0; i < NCLS; i++) { e[i] = fexp(v[i] - m); sum += e[i]; }
        float inv = 1.0f / sum;
#pragma unroll
        for (int i = 0; i < NCLS; i++) row[i] = e[i] * inv;
        g_segpred[base + tid] = am;
    }
    __syncthreads();

    float* dst = probs_out + (size_t)base * NCLS;
    for (int i = tid; i < tot; i += 256) {
        int row = i / NCLS, col = i - row * NCLS;
        dst[i] = s[row * 21 + col];
    }
}

// --- stream C: segment_min via smem privatization ---
__global__ void k_segmin(const int* __restrict__ pid, const int* __restrict__ nid) {
    __shared__ int sm[NPROP];
    int tid = threadIdx.x;
    for (int i = tid; i < NPROP; i += blockDim.x) sm[i] = 0x7FFFFFFF;
    __syncthreads();
    int stride = gridDim.x * blockDim.x;
    for (int m = blockIdx.x * blockDim.x + tid; m < NPAIR; m += stride)
        atomicMin(&sm[pid[m]], nid[m]);
    __syncthreads();
    for (int i = tid; i < NPROP; i += blockDim.x)
        if (sm[i] != 0x7FFFFFFF) atomicMin(&g_rep_p[i * PAD], sm[i]);
}

// --- joined: counts via popc + score via set-bit gather, one pass over bits.
// Each block covers 256 consecutive words -> spans at most 2 proposals.
__global__ void k_count_score(const float* __restrict__ probs) {
    __shared__ int   s_cnt[2];
    __shared__ float s_scr[2];
    int tid = threadIdx.x;
    if (tid < 2) { s_cnt[tid] = 0; s_scr[tid] = 0.0f; }
    __syncthreads();

    int t = blockIdx.x * 256 + tid;          // word index (exact grid)
    int pbase = (blockIdx.x * 256) / WPP;
    int p = t / WPP;
    unsigned int w = g_bits[t];
    if (w) {
        int r = g_rep_p[p * PAD];
        if (r > NPTS - 1) r = NPTS - 1;
        int inst = g_segpred[r];
        int j = t - p * WPP;
        float sum = 0.0f;
        unsigned int ww = w;
        while (ww) {
            int b = __ffs(ww) - 1;
            ww &= ww - 1;
            int n = j * 32 + b;
            sum += __ldg(&probs[(size_t)n * NCLS + inst]);
        }
        atomicAdd(&s_cnt[p - pbase], __popc(w));
        atomicAdd(&s_scr[p - pbase], sum);
    }
    __syncthreads();
    if (tid < 2) {
        int pp = pbase + tid;
        if (pp < NPROP && s_cnt[tid]) {
            atomicAdd(&g_count_p[pp * PAD], s_cnt[tid]);
            atomicAdd(&g_score_p[pp * PAD], s_scr[tid]);
        }
    }
}

// --- mask expansion (warp-coalesced 512B stores) + fused finalize in block 0 ---
__global__ void k_masks_final(float* __restrict__ out_masks,
                              float* __restrict__ out_scores,
                              float* __restrict__ out_classes) {
    int tid = threadIdx.x;
    if (blockIdx.x == 0 && tid < NPROP) {
        int c = g_count_p[tid * PAD];
        int flag = (c > THRESH) ? 1 : 0;
        int cm = c > 1 ? c : 1;
        int r = g_rep_p[tid * PAD];
        if (r > NPTS - 1) r = NPTS - 1;
        int inst = g_segpred[r];
        out_scores[tid]  = flag ? (g_score_p[tid * PAD] / (float)cm) : 0.0f;
        out_classes[tid] = flag ? (float)inst : -1.0f;
    }

    int t = blockIdx.x * blockDim.x + tid;   // word index (exact grid)
    int lane = tid & 31;
    int p = t / WPP;
    unsigned int w = g_bits[t];
    if (g_count_p[p * PAD] <= THRESH) w = 0u;

    size_t warp_word0 = (size_t)(t - lane);
    float4* dst = (float4*)out_masks + warp_word0 * 8;   // 8 float4 per word
    int nib = (lane & 7) * 4;
#pragma unroll
    for (int i = 0; i < 8; i++) {
        unsigned int src = __shfl_sync(0xFFFFFFFFu, w, i * 4 + (lane >> 3));
        float4 f;
        f.x = (float)((src >> (nib + 0)) & 1u);
        f.y = (float)((src >> (nib + 1)) & 1u);
        f.z = (float)((src >> (nib + 2)) & 1u);
        f.w = (float)((src >> (nib + 3)) & 1u);
        dst[(size_t)i * 32 + lane] = f;
    }
}

extern "C" void kernel_launch(void* const* d_in, const int* in_sizes, int n_in,
                              void* d_out, int out_size) {
    const float* logit = (const float*)d_in[0];
    const float* bias  = (const float*)d_in[1];
    // d_in[2] = coord: dead (center_pred never returned)
    const int* pid = (const int*)d_in[3];
    const int* nid = (const int*)d_in[4];

    float* out = (float*)d_out;
    float* out_scores  = out + OFF_SCORES;
    float* out_masks   = out + OFF_MASKS;
    float* out_classes = out + OFF_CLASSES;
    float* out_bias    = out + OFF_BIAS;
    float* out_probs   = out + OFF_PROBS;

    static cudaStream_t sB = nullptr, sC = nullptr, sD = nullptr;
    static cudaEvent_t eRoot, eB, eC, eD;
    if (!sB) {
        cudaStreamCreateWithFlags(&sB, cudaStreamNonBlocking);
        cudaStreamCreateWithFlags(&sC, cudaStreamNonBlocking);
        cudaStreamCreateWithFlags(&sD, cudaStreamNonBlocking);
        cudaEventCreateWithFlags(&eRoot, cudaEventDisableTiming);
        cudaEventCreateWithFlags(&eB, cudaEventDisableTiming);
        cudaEventCreateWithFlags(&eC, cudaEventDisableTiming);
        cudaEventCreateWithFlags(&eD, cudaEventDisableTiming);
    }

    // fork
    cudaEventRecord(eRoot, 0);
    cudaStreamWaitEvent(sB, eRoot, 0);
    cudaStreamWaitEvent(sC, eRoot, 0);
    cudaStreamWaitEvent(sD, eRoot, 0);

    // stream 0: zero bitmask -> dedupe scatter (no softmax/segmin dependency)
    k_zero_bits<<<(int)((WORDS / 4 + 255) / 256), 256>>>();
    k_scatter_lite<<<(NPAIR + 1023) / 1024, 1024>>>(pid, nid);
    // stream B: softmax (probs + segpred)
    k_softmax<<<(NPTS + 255) / 256, 256, 0, sB>>>(logit, out_probs);
    // stream C: counter init -> segmin
    k_init_small<<<(NPROP * PAD + 255) / 256, 256, 0, sC>>>();
    k_segmin<<<148, 512, 0, sC>>>(pid, nid);
    // stream D: bias passthrough
    k_bias<<<(NPTS * 3 / 4 + 255) / 256, 256, 0, sD>>>(bias, out_bias);

    // join B and C before count/score pass
    cudaEventRecord(eB, sB);
    cudaEventRecord(eC, sC);
    cudaStreamWaitEvent(0, eB, 0);
    cudaStreamWaitEvent(0, eC, 0);

    k_count_score<<<(int)(WORDS / 256), 256>>>(out_probs);
    k_masks_final<<<(int)(WORDS / 256), 256>>>(out_masks, out_scores, out_classes);

    // join D at the end
    cudaEventRecord(eD, sD);
    cudaStreamWaitEvent(0, eD, 0);
}

// round 8
// speedup vs baseline: 1.1897x; 1.1897x over previous
#include <cuda_runtime.h>
#include <cstdint>

// Problem constants
#define NPTS 200000
#define NCLS 20
#define NPROP 256
#define NPAIR 400000
#define THRESH 100

// Derived
#define WPP (NPTS / 32)                 // 6250 words per proposal
#define WORDS ((size_t)NPROP * WPP)     // 1,600,000 words

// Output layout (float32, concatenated in return order)
#define OFF_SCORES  ((size_t)0)
#define OFF_MASKS   ((size_t)256)
#define OFF_CLASSES ((size_t)(256 + (size_t)NPROP * NPTS))
#define OFF_BIAS    (OFF_CLASSES + 256)
#define OFF_PROBS   (OFF_BIAS + (size_t)NPTS * 3)

#define PAD 32   // 128B stride between per-proposal counters

// Scratch (device globals: allocation-free)
__device__ unsigned int g_bits[WORDS];          // 6.4 MB dedupe bitmask
__device__ unsigned char g_first[NPAIR];        // per-pair first-setter verdict
__device__ int   g_rep_p[NPROP * PAD];
__device__ int   g_count_p[NPROP * PAD];
__device__ float g_score_p[NPROP * PAD];
__device__ int   g_segpred[NPTS];

// Fast exp on FMA pipe (no MUFU). rel err ~2e-6.
__device__ __forceinline__ float fexp(float x) {
    const float MAGIC = 12582912.0f;           // 1.5 * 2^23
    float t = fmaf(x, 1.4426950408889634f, MAGIC);
    int   n = __float_as_int(t) - 0x4B400000;
    float f = fmaf(x, 1.4426950408889634f, -(t - MAGIC));
    float p = 1.3333558146e-3f;
    p = fmaf(p, f, 9.6181291076e-3f);
    p = fmaf(p, f, 5.5504108664e-2f);
    p = fmaf(p, f, 2.4022650696e-1f);
    p = fmaf(p, f, 6.9314718056e-1f);
    p = fmaf(p, f, 1.0f);
    return __int_as_float(__float_as_int(p) + (n << 23));
}

// --- stream 0: dedupe scatter (only dep: zeroed bitmask). Records verdicts. ---
__global__ void __launch_bounds__(1024)
k_scatter_lite(const int* __restrict__ pid, const int* __restrict__ nid) {
    int m = blockIdx.x * blockDim.x + threadIdx.x;
    if (m >= NPAIR) return;
    size_t bit = (size_t)pid[m] * NPTS + nid[m];
    unsigned int msk = 1u << (bit & 31u);
    unsigned int old = atomicOr(&g_bits[bit >> 5], msk);
    g_first[m] = (old & msk) ? 0 : 1;
}

// --- stream D: bias passthrough (independent) ---
__global__ void k_bias(const float* __restrict__ bias, float* __restrict__ bias_out) {
    int t = blockIdx.x * blockDim.x + threadIdx.x;
    if (t < NPTS * 3 / 4) ((float4*)bias_out)[t] = ((const float4*)bias)[t];
}

// --- stream B: staged softmax + argmax (padded smem rows, FMA exp) ---
__global__ void k_softmax(const float* __restrict__ logit,
                          float* __restrict__ probs_out) {
    __shared__ float s[256 * 21];   // 21 KB
    int tid  = threadIdx.x;
    int base = blockIdx.x * 256;
    int count = NPTS - base;
    if (count > 256) count = 256;
    int tot = count * NCLS;

    const float* src = logit + (size_t)base * NCLS;
    for (int i = tid; i < tot; i += 256) {
        int row = i / NCLS, col = i - row * NCLS;
        s[row * 21 + col] = src[i];
    }
    __syncthreads();

    if (tid < count) {
        float* row = s + tid * 21;
        float v[NCLS];
#pragma unroll
        for (int i = 0; i < NCLS; i++) v[i] = row[i];
        float m = v[0]; int am = 0;
#pragma unroll
        for (int i = 1; i < NCLS; i++) if (v[i] > m) { m = v[i]; am = i; }
        float e[NCLS]; float sum = 0.0f;
#pragma unroll
        for (int i = 0; i < NCLS; i++) { e[i] = fexp(v[i] - m); sum += e[i]; }
        float inv = 1.0f / sum;
#pragma unroll
        for (int i = 0; i < NCLS; i++) row[i] = e[i] * inv;
        g_segpred[base + tid] = am;
    }
    __syncthreads();

    float* dst = probs_out + (size_t)base * NCLS;
    for (int i = tid; i < tot; i += 256) {
        int row = i / NCLS, col = i - row * NCLS;
        dst[i] = s[row * 21 + col];
    }
}

// --- stream C: segment_min via smem privatization (g_rep_p pre-memset 0x7F) ---
__global__ void k_segmin(const int* __restrict__ pid, const int* __restrict__ nid) {
    __shared__ int sm[NPROP];
    int tid = threadIdx.x;
    for (int i = tid; i < NPROP; i += blockDim.x) sm[i] = 0x7FFFFFFF;
    __syncthreads();
    int stride = gridDim.x * blockDim.x;
    for (int m = blockIdx.x * blockDim.x + tid; m < NPAIR; m += stride)
        atomicMin(&sm[pid[m]], nid[m]);
    __syncthreads();
    for (int i = tid; i < NPROP; i += blockDim.x)
        if (sm[i] != 0x7FFFFFFF) atomicMin(&g_rep_p[i * PAD], sm[i]);
}

// --- joined: gather scores/counts for unique pairs only ---
__global__ void __launch_bounds__(1024, 2)
k_gather(const int* __restrict__ pid, const int* __restrict__ nid,
         const float* __restrict__ probs) {
    __shared__ int   s_inst[NPROP];
    __shared__ int   s_cnt[NPROP];
    __shared__ float s_scr[NPROP];
    int tid = threadIdx.x;
    if (tid < NPROP) {
        int r = g_rep_p[tid * PAD];
        if (r > NPTS - 1) r = NPTS - 1;
        s_inst[tid] = g_segpred[r];
        s_cnt[tid] = 0;
        s_scr[tid] = 0.0f;
    }
    __syncthreads();

    int stride = gridDim.x * blockDim.x;
    for (int m = blockIdx.x * blockDim.x + tid; m < NPAIR; m += stride) {
        if (g_first[m]) {
            int p = pid[m];
            int n = nid[m];
            atomicAdd(&s_cnt[p], 1);
            atomicAdd(&s_scr[p], __ldg(&probs[(size_t)n * NCLS + s_inst[p]]));
        }
    }
    __syncthreads();
    if (tid < NPROP) {
        if (s_cnt[tid]) {
            atomicAdd(&g_count_p[tid * PAD], s_cnt[tid]);
            atomicAdd(&g_score_p[tid * PAD], s_scr[tid]);
        }
    }
}

// --- mask expansion (warp-coalesced 512B stores) + fused finalize in block 0 ---
__global__ void k_masks_final(float* __restrict__ out_masks,
                              float* __restrict__ out_scores,
                              float* __restrict__ out_classes) {
    int tid = threadIdx.x;
    if (blockIdx.x == 0 && tid < NPROP) {
        int c = g_count_p[tid * PAD];
        int flag = (c > THRESH) ? 1 : 0;
        int cm = c > 1 ? c : 1;
        int r = g_rep_p[tid * PAD];
        if (r > NPTS - 1) r = NPTS - 1;
        int inst = g_segpred[r];
        out_scores[tid]  = flag ? (g_score_p[tid * PAD] / (float)cm) : 0.0f;
        out_classes[tid] = flag ? (float)inst : -1.0f;
    }

    int t = blockIdx.x * blockDim.x + tid;   // word index (exact grid)
    int lane = tid & 31;
    int p = t / WPP;
    unsigned int w = g_bits[t];
    if (g_count_p[p * PAD] <= THRESH) w = 0u;

    size_t warp_word0 = (size_t)(t - lane);
    float4* dst = (float4*)out_masks + warp_word0 * 8;   // 8 float4 per word
    int nib = (lane & 7) * 4;
#pragma unroll
    for (int i = 0; i < 8; i++) {
        unsigned int src = __shfl_sync(0xFFFFFFFFu, w, i * 4 + (lane >> 3));
        float4 f;
        f.x = (float)((src >> (nib + 0)) & 1u);
        f.y = (float)((src >> (nib + 1)) & 1u);
        f.z = (float)((src >> (nib + 2)) & 1u);
        f.w = (float)((src >> (nib + 3)) & 1u);
        dst[(size_t)i * 32 + lane] = f;
    }
}

extern "C" void kernel_launch(void* const* d_in, const int* in_sizes, int n_in,
                              void* d_out, int out_size) {
    const float* logit = (const float*)d_in[0];
    const float* bias  = (const float*)d_in[1];
    // d_in[2] = coord: dead
    const int* pid = (const int*)d_in[3];
    const int* nid = (const int*)d_in[4];

    float* out = (float*)d_out;
    float* out_scores  = out + OFF_SCORES;
    float* out_masks   = out + OFF_MASKS;
    float* out_classes = out + OFF_CLASSES;
    float* out_bias    = out + OFF_BIAS;
    float* out_probs   = out + OFF_PROBS;

    static cudaStream_t sB = nullptr, sC = nullptr, sD = nullptr;
    static cudaEvent_t eRoot, eB, eC, eD;
    static void *a_bits = nullptr, *a_rep = nullptr, *a_cnt = nullptr, *a_scr = nullptr;
    if (!sB) {
        cudaStreamCreateWithFlags(&sB, cudaStreamNonBlocking);
        cudaStreamCreateWithFlags(&sC, cudaStreamNonBlocking);
        cudaStreamCreateWithFlags(&sD, cudaStreamNonBlocking);
        cudaEventCreateWithFlags(&eRoot, cudaEventDisableTiming);
        cudaEventCreateWithFlags(&eB, cudaEventDisableTiming);
        cudaEventCreateWithFlags(&eC, cudaEventDisableTiming);
        cudaEventCreateWithFlags(&eD, cudaEventDisableTiming);
        cudaGetSymbolAddress(&a_bits, g_bits);
        cudaGetSymbolAddress(&a_rep,  g_rep_p);
        cudaGetSymbolAddress(&a_cnt,  g_count_p);
        cudaGetSymbolAddress(&a_scr,  g_score_p);
    }

    // fork
    cudaEventRecord(eRoot, 0);
    cudaStreamWaitEvent(sB, eRoot, 0);
    cudaStreamWaitEvent(sC, eRoot, 0);
    cudaStreamWaitEvent(sD, eRoot, 0);

    // stream 0: zero bitmask (memset node) -> dedupe scatter (no other deps)
    cudaMemsetAsync(a_bits, 0, WORDS * 4, 0);
    k_scatter_lite<<<(NPAIR + 1023) / 1024, 1024>>>(pid, nid);
    // stream B: softmax (probs + segpred)
    k_softmax<<<(NPTS + 255) / 256, 256, 0, sB>>>(logit, out_probs);
    // stream C: memset counters -> segmin
    cudaMemsetAsync(a_rep, 0x7F, NPROP * PAD * 4, sC);   // 0x7F7F7F7F > NPTS
    cudaMemsetAsync(a_cnt, 0, NPROP * PAD * 4, sC);
    cudaMemsetAsync(a_scr, 0, NPROP * PAD * 4, sC);
    k_segmin<<<148, 512, 0, sC>>>(pid, nid);
    // stream D: bias passthrough
    k_bias<<<(NPTS * 3 / 4 + 255) / 256, 256, 0, sD>>>(bias, out_bias);

    // join B and C into stream 0 (stream 0 already holds the scatter dep)
    cudaEventRecord(eB, sB);
    cudaEventRecord(eC, sC);
    cudaStreamWaitEvent(0, eB, 0);
    cudaStreamWaitEvent(0, eC, 0);

    k_gather<<<296, 1024>>>(pid, nid, out_probs);
    k_masks_final<<<(int)(WORDS / 256), 256>>>(out_masks, out_scores, out_classes);

    // join D at the end
    cudaEventRecord(eD, sD);
    cudaStreamWaitEvent(0, eD, 0);
}